// round 2
// baseline (speedup 1.0000x reference)
#include <cuda_runtime.h>
#include <cuda_bf16.h>

#define NN   50000
#define EE   800000
#define FIN  32
#define HH   128
#define LN_EPS 1e-5f

// ---------------- scratch (static device allocations only) ----------------
__device__ float g_h0[NN * HH];   // post input-proj activations (also residual)
__device__ float g_h1[NN * HH];   // post layer-0 activations
__device__ float g_agg[NN * HH];  // scatter accumulator
__device__ float g_inv[NN];       // 1 / max(deg, 1)
__device__ int   g_cnt[NN];       // in-degree

// ---------------- zero agg (+ optionally cnt) ----------------
__global__ void zero_kernel(int with_cnt) {
    int i = blockIdx.x * blockDim.x + threadIdx.x;
    if (i < NN * HH / 4) {
        reinterpret_cast<float4*>(g_agg)[i] = make_float4(0.f, 0.f, 0.f, 0.f);
    }
    if (with_cnt && i < NN) g_cnt[i] = 0;
}

// ---------------- input projection: h0 = relu(x @ w_in + b_in) ----------------
__global__ void input_proj_kernel(const float* __restrict__ x,
                                  const float* __restrict__ w,
                                  const float* __restrict__ b) {
    __shared__ float sw[FIN * HH];
    __shared__ float sb[HH];
    int tid = threadIdx.x;  // 256
    for (int i = tid; i < FIN * HH; i += 256) sw[i] = w[i];
    if (tid < HH) sb[tid] = b[tid];
    __syncthreads();

    int j = tid & 127;
    int half = tid >> 7;
    for (int n = blockIdx.x * 2 + half; n < NN; n += gridDim.x * 2) {
        const float4* xr = reinterpret_cast<const float4*>(x + n * FIN);
        float acc = sb[j];
#pragma unroll
        for (int k4 = 0; k4 < FIN / 4; k4++) {
            float4 xv = xr[k4];
            int k = k4 * 4;
            acc = fmaf(xv.x, sw[(k + 0) * HH + j], acc);
            acc = fmaf(xv.y, sw[(k + 1) * HH + j], acc);
            acc = fmaf(xv.z, sw[(k + 2) * HH + j], acc);
            acc = fmaf(xv.w, sw[(k + 3) * HH + j], acc);
        }
        g_h0[n * HH + j] = fmaxf(acc, 0.f);
    }
}

// ---------------- degree count + reciprocal ----------------
__global__ void count_kernel(const int* __restrict__ tgt) {
    int i = blockIdx.x * blockDim.x + threadIdx.x;
    if (i < EE) atomicAdd(&g_cnt[tgt[i]], 1);
}

__global__ void inv_kernel() {
    int i = blockIdx.x * blockDim.x + threadIdx.x;
    if (i < NN) g_inv[i] = 1.0f / fmaxf((float)g_cnt[i], 1.0f);
}

// ---------------- scatter: agg[tgt] += h[src]  (float4 atomics, sm_90+) ----------------
template <int WHICH>
__global__ void scatter_kernel(const int* __restrict__ src,
                               const int* __restrict__ tgt) {
    const float* __restrict__ h = (WHICH == 0) ? g_h0 : g_h1;
    int idx = blockIdx.x * blockDim.x + threadIdx.x;
    int e = idx >> 5;               // 32 threads per edge
    if (e >= EE) return;
    int f = (idx & 31) << 2;        // 4 features per thread
    int s = __ldg(&src[e]);
    int t = __ldg(&tgt[e]);
    float4 v = *reinterpret_cast<const float4*>(h + s * HH + f);
    atomicAdd(reinterpret_cast<float4*>(g_agg + t * HH + f), v);
}

// ---------------- fused GCN layer: tmp = h@ws + bs + (agg/deg)@wn + bn ; LN ; [relu+res] ----------------
// LAYER 0: h_in = g_h0, out = g_h1, relu+residual applied after LN
// LAYER 1: h_in = g_h1, out = param (d_out), LN only
template <int LAYER>
__global__ void __launch_bounds__(512, 1)
gcn_kernel(const float* __restrict__ ws, const float* __restrict__ bs,
           const float* __restrict__ wn, const float* __restrict__ bn,
           const float* __restrict__ gamma, const float* __restrict__ beta,
           float* __restrict__ out_param) {
    extern __shared__ float sm[];
    float* sW0 = sm;                 // [128][128] self weight
    float* sW1 = sm + HH * HH;       // [128][128] neigh weight
    float* sHS = sm + 2 * HH * HH;   // [16][128] staged h rows
    float* sAS = sHS + 16 * HH;      // [16][128] staged normalized agg rows
    float* sOB = sAS + 16 * HH;      // [16][128] pre-LN outputs

    const float* __restrict__ h_in = (LAYER == 0) ? g_h0 : g_h1;
    float* __restrict__ out = (LAYER == 0) ? g_h1 : out_param;

    int tid = threadIdx.x;
    for (int i = tid; i < HH * HH; i += 512) {
        sW0[i] = ws[i];
        sW1[i] = wn[i];
    }

    int j = tid & 127;       // output column
    int g = tid >> 7;        // node sub-group 0..3
    float bias_j = __ldg(&bs[j]) + __ldg(&bn[j]);

    int lane = tid & 31;
    int warp = tid >> 5;     // 0..15, one warp per node in LN phase
    float ga[4], be[4];
#pragma unroll
    for (int m = 0; m < 4; m++) {
        ga[m] = __ldg(&gamma[lane + 32 * m]);
        be[m] = __ldg(&beta[lane + 32 * m]);
    }
    __syncthreads();

    const int NT = NN / 16;  // 3125 tiles of 16 nodes
    for (int tile = blockIdx.x; tile < NT; tile += gridDim.x) {
        int base = tile * 16;

        // ---- stage activations for 16 nodes ----
        {
            int row = tid >> 5;   // 0..15
            int f4 = tid & 31;
            int node = base + row;
            float4 hv = *reinterpret_cast<const float4*>(h_in + node * HH + f4 * 4);
            float4 av = *reinterpret_cast<const float4*>(g_agg + node * HH + f4 * 4);
            float iv = __ldg(&g_inv[node]);
            av.x *= iv; av.y *= iv; av.z *= iv; av.w *= iv;
            reinterpret_cast<float4*>(sHS)[row * 32 + f4] = hv;
            reinterpret_cast<float4*>(sAS)[row * 32 + f4] = av;
        }
        __syncthreads();

        // ---- GEMM: 4 nodes per thread, K = 128, both matrices ----
        float acc[4];
#pragma unroll
        for (int i = 0; i < 4; i++) acc[i] = bias_j;

        const float4* hs4 = reinterpret_cast<const float4*>(sHS) + (g * 4) * 32;
        const float4* as4 = reinterpret_cast<const float4*>(sAS) + (g * 4) * 32;

#pragma unroll 4
        for (int k4 = 0; k4 < 32; k4++) {
            float hva[4][4], ava[4][4];
#pragma unroll
            for (int i = 0; i < 4; i++) {
                float4 t = hs4[i * 32 + k4];
                hva[i][0] = t.x; hva[i][1] = t.y; hva[i][2] = t.z; hva[i][3] = t.w;
                float4 u = as4[i * 32 + k4];
                ava[i][0] = u.x; ava[i][1] = u.y; ava[i][2] = u.z; ava[i][3] = u.w;
            }
#pragma unroll
            for (int kk = 0; kk < 4; kk++) {
                int k = k4 * 4 + kk;
                float w0 = sW0[k * HH + j];
                float w1 = sW1[k * HH + j];
#pragma unroll
                for (int i = 0; i < 4; i++) {
                    acc[i] = fmaf(hva[i][kk], w0, acc[i]);
                    acc[i] = fmaf(ava[i][kk], w1, acc[i]);
                }
            }
        }

#pragma unroll
        for (int i = 0; i < 4; i++) sOB[(g * 4 + i) * HH + j] = acc[i];
        __syncthreads();

        // ---- LayerNorm (+ relu + residual for layer 0): one warp per node ----
        {
            int node = base + warp;
            float v[4];
            float s = 0.f, q = 0.f;
#pragma unroll
            for (int m = 0; m < 4; m++) {
                v[m] = sOB[warp * HH + lane + 32 * m];
                s += v[m];
                q += v[m] * v[m];
            }
#pragma unroll
            for (int o = 16; o > 0; o >>= 1) {
                s += __shfl_xor_sync(0xffffffffu, s, o);
                q += __shfl_xor_sync(0xffffffffu, q, o);
            }
            float mean = s * (1.0f / HH);
            float var = q * (1.0f / HH) - mean * mean;
            float rstd = rsqrtf(var + LN_EPS);
#pragma unroll
            for (int m = 0; m < 4; m++) {
                float y = (v[m] - mean) * rstd * ga[m] + be[m];
                if (LAYER == 0) y = fmaxf(y, 0.f) + h_in[node * HH + lane + 32 * m];
                out[node * HH + lane + 32 * m] = y;
            }
        }
        __syncthreads();  // protect sOB/sHS/sAS before next tile's staging
    }
}

// ---------------- launch ----------------
extern "C" void kernel_launch(void* const* d_in, const int* in_sizes, int n_in,
                              void* d_out, int out_size) {
    const float* x    = (const float*)d_in[0];
    const int*   ei   = (const int*)d_in[1];
    const float* w_in = (const float*)d_in[2];
    const float* b_in = (const float*)d_in[3];
    const float* ws0  = (const float*)d_in[4];
    const float* bs0  = (const float*)d_in[5];
    const float* wn0  = (const float*)d_in[6];
    const float* bn0  = (const float*)d_in[7];
    const float* g0   = (const float*)d_in[8];
    const float* be0  = (const float*)d_in[9];
    const float* ws1  = (const float*)d_in[10];
    const float* bs1  = (const float*)d_in[11];
    const float* wn1  = (const float*)d_in[12];
    const float* bn1  = (const float*)d_in[13];
    const float* g1   = (const float*)d_in[14];
    const float* be1  = (const float*)d_in[15];
    float* out = (float*)d_out;

    const int* src = ei;
    const int* tgt = ei + EE;

    const int SMEM = (2 * HH * HH + 3 * 16 * HH) * (int)sizeof(float);  // 155648 B
    cudaFuncSetAttribute(gcn_kernel<0>, cudaFuncAttributeMaxDynamicSharedMemorySize, SMEM);
    cudaFuncSetAttribute(gcn_kernel<1>, cudaFuncAttributeMaxDynamicSharedMemorySize, SMEM);

    // pipeline (default stream, graph-capturable)
    zero_kernel<<<NN * HH / 4 / 256, 256>>>(1);
    input_proj_kernel<<<512, 256>>>(x, w_in, b_in);
    count_kernel<<<(EE + 255) / 256, 256>>>(tgt);
    inv_kernel<<<(NN + 255) / 256, 256>>>();
    scatter_kernel<0><<<EE * 32 / 256, 256>>>(src, tgt);
    gcn_kernel<0><<<148, 512, SMEM>>>(ws0, bs0, wn0, bn0, g0, be0, nullptr);
    zero_kernel<<<NN * HH / 4 / 256, 256>>>(0);
    scatter_kernel<1><<<EE * 32 / 256, 256>>>(src, tgt);
    gcn_kernel<1><<<148, 512, SMEM>>>(ws1, bs1, wn1, bn1, g1, be1, out);
}

// round 6
// speedup vs baseline: 1.2401x; 1.2401x over previous
#include <cuda_runtime.h>
#include <cuda_bf16.h>

#define NN   50000
#define EE   800000
#define FIN  32
#define HH   128
#define LN_EPS 1e-5f

// ---------------- scratch (static device allocations only) ----------------
__device__ float g_h0[NN * HH];   // post input-proj activations (also residual)
__device__ float g_h1[NN * HH];   // post layer-0 activations
__device__ float g_agg[NN * HH];  // normalized neighbor mean
__device__ float g_inv[NN];       // 1 / max(deg, 1)
__device__ int   g_cnt[NN];       // in-degree
__device__ int   g_off[NN];       // CSR row starts
__device__ int   g_pos[NN];       // fill cursors
__device__ int   g_adj[EE];       // CSR adjacency (src node per slot)

// ---------------- packed f32x2 fma helper ----------------
__device__ __forceinline__ void fma2(unsigned long long& d,
                                     unsigned long long a,
                                     unsigned long long b) {
    asm("fma.rn.f32x2 %0, %1, %2, %3;" : "=l"(d) : "l"(a), "l"(b), "l"(d));
}

__device__ __forceinline__ float f2fold(unsigned long long a, float bias) {
    float lo, hi;
    asm("mov.b64 {%0,%1}, %2;" : "=f"(lo), "=f"(hi) : "l"(a));
    return lo + hi + bias;
}

// ---------------- zero degree counters ----------------
__global__ void zero_cnt_kernel() {
    int i = blockIdx.x * blockDim.x + threadIdx.x;
    if (i < NN) g_cnt[i] = 0;
}

// ---------------- input projection: h0 = relu(x @ w_in + b_in) ----------------
__global__ void input_proj_kernel(const float* __restrict__ x,
                                  const float* __restrict__ w,
                                  const float* __restrict__ b) {
    __shared__ float sw[FIN * HH];
    __shared__ float sb[HH];
    int tid = threadIdx.x;  // 256
    for (int i = tid; i < FIN * HH; i += 256) sw[i] = w[i];
    if (tid < HH) sb[tid] = b[tid];
    __syncthreads();

    int j = tid & 127;
    int half = tid >> 7;
    for (int n = blockIdx.x * 2 + half; n < NN; n += gridDim.x * 2) {
        const float4* xr = reinterpret_cast<const float4*>(x + n * FIN);
        float acc = sb[j];
#pragma unroll
        for (int k4 = 0; k4 < FIN / 4; k4++) {
            float4 xv = xr[k4];
            int k = k4 * 4;
            acc = fmaf(xv.x, sw[(k + 0) * HH + j], acc);
            acc = fmaf(xv.y, sw[(k + 1) * HH + j], acc);
            acc = fmaf(xv.z, sw[(k + 2) * HH + j], acc);
            acc = fmaf(xv.w, sw[(k + 3) * HH + j], acc);
        }
        g_h0[n * HH + j] = fmaxf(acc, 0.f);
    }
}

// ---------------- degree count ----------------
__global__ void count_kernel(const int* __restrict__ tgt) {
    int i = blockIdx.x * blockDim.x + threadIdx.x;
    if (i < EE) atomicAdd(&g_cnt[tgt[i]], 1);
}

// ---------------- single-block scan: offsets + cursors + inv-degree ----------------
__global__ void scan_kernel() {
    __shared__ int ssum[1024];
    const int C = 49;  // 1024 * 49 >= NN
    int t = threadIdx.x;
    int beg = t * C;
    int end = min(beg + C, NN);
    int s = 0;
    for (int i = beg; i < end; i++) s += g_cnt[i];
    ssum[t] = s;
    __syncthreads();
    // inclusive Hillis-Steele scan
    for (int off = 1; off < 1024; off <<= 1) {
        int v = ssum[t];
        int u = (t >= off) ? ssum[t - off] : 0;
        __syncthreads();
        ssum[t] = v + u;
        __syncthreads();
    }
    int run = ssum[t] - s;  // exclusive prefix for this chunk
    for (int i = beg; i < end; i++) {
        int c = g_cnt[i];
        g_off[i] = run;
        g_pos[i] = run;
        g_inv[i] = 1.0f / fmaxf((float)c, 1.0f);
        run += c;
    }
}

// ---------------- CSR fill ----------------
__global__ void fill_kernel(const int* __restrict__ src,
                            const int* __restrict__ tgt) {
    int e = blockIdx.x * blockDim.x + threadIdx.x;
    if (e < EE) {
        int p = atomicAdd(&g_pos[tgt[e]], 1);
        g_adj[p] = src[e];
    }
}

// ---------------- gather: agg[n] = mean over in-neighbors of h[src] ----------------
template <int WHICH>
__global__ void gather_kernel() {
    const float* __restrict__ h = (WHICH == 0) ? g_h0 : g_h1;
    int idx = blockIdx.x * blockDim.x + threadIdx.x;
    int node = idx >> 5;
    if (node >= NN) return;
    int lane = idx & 31;

    int beg = g_off[node];
    int cnt = g_cnt[node];
    float4 acc = make_float4(0.f, 0.f, 0.f, 0.f);

    int i = 0;
    for (; i + 4 <= cnt; i += 4) {
        int s0 = __ldg(&g_adj[beg + i + 0]);
        int s1 = __ldg(&g_adj[beg + i + 1]);
        int s2 = __ldg(&g_adj[beg + i + 2]);
        int s3 = __ldg(&g_adj[beg + i + 3]);
        float4 v0 = *reinterpret_cast<const float4*>(h + s0 * HH + lane * 4);
        float4 v1 = *reinterpret_cast<const float4*>(h + s1 * HH + lane * 4);
        float4 v2 = *reinterpret_cast<const float4*>(h + s2 * HH + lane * 4);
        float4 v3 = *reinterpret_cast<const float4*>(h + s3 * HH + lane * 4);
        acc.x += v0.x + v1.x + v2.x + v3.x;
        acc.y += v0.y + v1.y + v2.y + v3.y;
        acc.z += v0.z + v1.z + v2.z + v3.z;
        acc.w += v0.w + v1.w + v2.w + v3.w;
    }
    for (; i < cnt; i++) {
        int s = __ldg(&g_adj[beg + i]);
        float4 v = *reinterpret_cast<const float4*>(h + s * HH + lane * 4);
        acc.x += v.x; acc.y += v.y; acc.z += v.z; acc.w += v.w;
    }
    float iv = g_inv[node];
    acc.x *= iv; acc.y *= iv; acc.z *= iv; acc.w *= iv;
    *reinterpret_cast<float4*>(g_agg + node * HH + lane * 4) = acc;
}

// ---------------- fused GCN layer (FFMA2 GEMM + LN [+relu+residual]) ----------------
// tile = 64 nodes; 512 threads = 64 col-pairs x 8 node-groups; 8 nodes/thread.
// accumulate even/odd-k partial sums packed in f32x2, fold at epilogue.
template <int LAYER>
__global__ void __launch_bounds__(512, 1)
gcn_kernel(const float* __restrict__ ws, const float* __restrict__ bs,
           const float* __restrict__ wn, const float* __restrict__ bn,
           const float* __restrict__ gamma, const float* __restrict__ beta,
           float* __restrict__ out_param) {
    extern __shared__ float sm[];
    float* sWs = sm;                     // 16384 floats: packed [k4][j][4]
    float* sWn = sm + HH * HH;           // 16384 floats
    float* sH  = sm + 2 * HH * HH;       // 64 x 128 staged h rows (aliased by sOB)
    float* sA  = sH + 64 * HH;           // 64 x 128 staged agg rows
    float* sOB = sH;                     // pre-LN outputs alias sH

    const float* __restrict__ h_in = (LAYER == 0) ? g_h0 : g_h1;
    float* __restrict__ out = (LAYER == 0) ? g_h1 : out_param;

    int tid = threadIdx.x;

    // pack weights: sW[(k>>2)*512 + j*4 + (k&3)] = w[k*128 + j]
    for (int i = tid; i < HH * HH; i += 512) {
        int k = i >> 7, j = i & 127;
        int d = ((k >> 2) * HH + j) * 4 + (k & 3);
        sWs[d] = ws[i];
        sWn[d] = wn[i];
    }

    int j = tid & 63;   // column pair (j, j+64)
    int g = tid >> 6;   // node group 0..7
    float bias0 = __ldg(&bs[j]) + __ldg(&bn[j]);
    float bias1 = __ldg(&bs[j + 64]) + __ldg(&bn[j + 64]);

    int lane = tid & 31;
    int warp = tid >> 5;  // 0..15; each warp LNs 4 nodes
    float ga[4], be[4];
#pragma unroll
    for (int m = 0; m < 4; m++) {
        ga[m] = __ldg(&gamma[lane + 32 * m]);
        be[m] = __ldg(&beta[lane + 32 * m]);
    }
    __syncthreads();

    const ulonglong2* Ws2 = reinterpret_cast<const ulonglong2*>(sWs);
    const ulonglong2* Wn2 = reinterpret_cast<const ulonglong2*>(sWn);
    const ulonglong2* H2  = reinterpret_cast<const ulonglong2*>(sH);
    const ulonglong2* A2  = reinterpret_cast<const ulonglong2*>(sA);

    const int NT = (NN + 63) / 64;  // 782 tiles
    for (int tile = blockIdx.x; tile < NT; tile += gridDim.x) {
        int base = tile * 64;

        // ---- stage 64 node rows of h and agg (zeros for OOB) ----
        {
            int row = tid >> 3;            // 0..63
            int c4 = (tid & 7) * 4;        // float4 col base
            int node = base + row;
            float4 z = make_float4(0.f, 0.f, 0.f, 0.f);
#pragma unroll
            for (int q = 0; q < 4; q++) {
                float4 hv = z, av = z;
                if (node < NN) {
                    hv = *reinterpret_cast<const float4*>(h_in + node * HH + (c4 + q) * 4);
                    av = *reinterpret_cast<const float4*>(g_agg + node * HH + (c4 + q) * 4);
                }
                reinterpret_cast<float4*>(sH)[row * 32 + c4 + q] = hv;
                reinterpret_cast<float4*>(sA)[row * 32 + c4 + q] = av;
            }
        }
        __syncthreads();

        // ---- packed GEMM: 8 nodes x 2 cols per thread ----
        unsigned long long acc0[8], acc1[8];
#pragma unroll
        for (int i = 0; i < 8; i++) { acc0[i] = 0ull; acc1[i] = 0ull; }

        for (int k4 = 0; k4 < 32; k4++) {
            ulonglong2 wsa = Ws2[k4 * HH + j];
            ulonglong2 wsb = Ws2[k4 * HH + j + 64];
            ulonglong2 wna = Wn2[k4 * HH + j];
            ulonglong2 wnb = Wn2[k4 * HH + j + 64];
#pragma unroll
            for (int i = 0; i < 8; i++) {
                ulonglong2 hv = H2[(g * 8 + i) * 32 + k4];
                ulonglong2 av = A2[(g * 8 + i) * 32 + k4];
                fma2(acc0[i], hv.x, wsa.x);
                fma2(acc0[i], hv.y, wsa.y);
                fma2(acc0[i], av.x, wna.x);
                fma2(acc0[i], av.y, wna.y);
                fma2(acc1[i], hv.x, wsb.x);
                fma2(acc1[i], hv.y, wsb.y);
                fma2(acc1[i], av.x, wnb.x);
                fma2(acc1[i], av.y, wnb.y);
            }
        }
        __syncthreads();  // everyone done reading sH/sA before sOB aliasing write

#pragma unroll
        for (int i = 0; i < 8; i++) {
            int row = g * 8 + i;
            sOB[row * HH + j]      = f2fold(acc0[i], bias0);
            sOB[row * HH + j + 64] = f2fold(acc1[i], bias1);
        }
        __syncthreads();

        // ---- LayerNorm (+ relu + residual for layer 0): warp handles 4 nodes ----
#pragma unroll
        for (int it = 0; it < 4; it++) {
            int row = warp * 4 + it;
            int node = base + row;
            if (node < NN) {
                float v[4];
                float s = 0.f, q = 0.f;
#pragma unroll
                for (int m = 0; m < 4; m++) {
                    v[m] = sOB[row * HH + lane + 32 * m];
                    s += v[m];
                    q += v[m] * v[m];
                }
#pragma unroll
                for (int o = 16; o > 0; o >>= 1) {
                    s += __shfl_xor_sync(0xffffffffu, s, o);
                    q += __shfl_xor_sync(0xffffffffu, q, o);
                }
                float mean = s * (1.0f / HH);
                float var = q * (1.0f / HH) - mean * mean;
                float rstd = rsqrtf(var + LN_EPS);
#pragma unroll
                for (int m = 0; m < 4; m++) {
                    float y = (v[m] - mean) * rstd * ga[m] + be[m];
                    if (LAYER == 0)
                        y = fmaxf(y, 0.f) + h_in[node * HH + lane + 32 * m];
                    out[node * HH + lane + 32 * m] = y;
                }
            }
        }
        __syncthreads();  // protect sOB/sA before next tile staging
    }
}

// ---------------- launch ----------------
extern "C" void kernel_launch(void* const* d_in, const int* in_sizes, int n_in,
                              void* d_out, int out_size) {
    const float* x    = (const float*)d_in[0];
    const int*   ei   = (const int*)d_in[1];
    const float* w_in = (const float*)d_in[2];
    const float* b_in = (const float*)d_in[3];
    const float* ws0  = (const float*)d_in[4];
    const float* bs0  = (const float*)d_in[5];
    const float* wn0  = (const float*)d_in[6];
    const float* bn0  = (const float*)d_in[7];
    const float* g0   = (const float*)d_in[8];
    const float* be0  = (const float*)d_in[9];
    const float* ws1  = (const float*)d_in[10];
    const float* bs1  = (const float*)d_in[11];
    const float* wn1  = (const float*)d_in[12];
    const float* bn1  = (const float*)d_in[13];
    const float* g1   = (const float*)d_in[14];
    const float* be1  = (const float*)d_in[15];
    float* out = (float*)d_out;

    const int* src = ei;
    const int* tgt = ei + EE;

    const int SMEM = (2 * HH * HH + 2 * 64 * HH) * (int)sizeof(float);  // 196608 B
    cudaFuncSetAttribute(gcn_kernel<0>, cudaFuncAttributeMaxDynamicSharedMemorySize, SMEM);
    cudaFuncSetAttribute(gcn_kernel<1>, cudaFuncAttributeMaxDynamicSharedMemorySize, SMEM);

    zero_cnt_kernel<<<(NN + 255) / 256, 256>>>();
    input_proj_kernel<<<512, 256>>>(x, w_in, b_in);
    count_kernel<<<(EE + 255) / 256, 256>>>(tgt);
    scan_kernel<<<1, 1024>>>();
    fill_kernel<<<(EE + 255) / 256, 256>>>(src, tgt);
    gather_kernel<0><<<(NN * 32 + 255) / 256, 256>>>();
    gcn_kernel<0><<<148, 512, SMEM>>>(ws0, bs0, wn0, bn0, g0, be0, nullptr);
    gather_kernel<1><<<(NN * 32 + 255) / 256, 256>>>();
    gcn_kernel<1><<<148, 512, SMEM>>>(ws1, bs1, wn1, bn1, g1, be1, out);
}

// round 7
// speedup vs baseline: 1.5764x; 1.2711x over previous
#include <cuda_runtime.h>
#include <cuda_bf16.h>

#define NN   50000
#define EE   800000
#define FIN  32
#define HH   128
#define LN_EPS 1e-5f
#define NB   ((NN + 255) / 256)   // 196 scan blocks

// ---------------- scratch (static device allocations only) ----------------
__device__ float g_h0[NN * HH];   // post input-proj activations (also residual)
__device__ float g_h1[NN * HH];   // post layer-0 activations
__device__ float g_agg[NN * HH];  // normalized neighbor mean
__device__ float g_inv[NN];       // 1 / max(deg, 1)
__device__ int   g_cnt[NN];       // in-degree
__device__ int   g_off[NN];       // CSR row starts
__device__ int   g_pos[NN];       // fill cursors
__device__ int   g_adj[EE];       // CSR adjacency (src node per slot)
__device__ int   g_bsum[NB];      // per-block scan totals
__device__ int   g_bpre[NB];      // exclusive prefix of block totals

// ---------------- packed f32x2 fma helper ----------------
__device__ __forceinline__ void fma2(unsigned long long& d,
                                     unsigned long long a,
                                     unsigned long long b) {
    asm("fma.rn.f32x2 %0, %1, %2, %3;" : "=l"(d) : "l"(a), "l"(b), "l"(d));
}

__device__ __forceinline__ float f2fold(unsigned long long a, float bias) {
    float lo, hi;
    asm("mov.b64 {%0,%1}, %2;" : "=f"(lo), "=f"(hi) : "l"(a));
    return lo + hi + bias;
}

// ---------------- zero degree counters ----------------
__global__ void zero_cnt_kernel() {
    int i = blockIdx.x * blockDim.x + threadIdx.x;
    if (i < NN) g_cnt[i] = 0;
}

// ---------------- input projection: h0 = relu(x @ w_in + b_in) ----------------
__global__ void input_proj_kernel(const float* __restrict__ x,
                                  const float* __restrict__ w,
                                  const float* __restrict__ b) {
    __shared__ float sw[FIN * HH];
    __shared__ float sb[HH];
    int tid = threadIdx.x;  // 256
    for (int i = tid; i < FIN * HH; i += 256) sw[i] = w[i];
    if (tid < HH) sb[tid] = b[tid];
    __syncthreads();

    int j = tid & 127;
    int half = tid >> 7;
    for (int n = blockIdx.x * 2 + half; n < NN; n += gridDim.x * 2) {
        const float4* xr = reinterpret_cast<const float4*>(x + n * FIN);
        float acc = sb[j];
#pragma unroll
        for (int k4 = 0; k4 < FIN / 4; k4++) {
            float4 xv = xr[k4];
            int k = k4 * 4;
            acc = fmaf(xv.x, sw[(k + 0) * HH + j], acc);
            acc = fmaf(xv.y, sw[(k + 1) * HH + j], acc);
            acc = fmaf(xv.z, sw[(k + 2) * HH + j], acc);
            acc = fmaf(xv.w, sw[(k + 3) * HH + j], acc);
        }
        g_h0[n * HH + j] = fmaxf(acc, 0.f);
    }
}

// ---------------- degree count ----------------
__global__ void count_kernel(const int* __restrict__ tgt) {
    int i = blockIdx.x * blockDim.x + threadIdx.x;
    if (i < EE) atomicAdd(&g_cnt[tgt[i]], 1);
}

// ---------------- parallel scan, stage 1: per-block exclusive prefix ----------------
__global__ void scan1_kernel() {
    int blk = blockIdx.x;
    int t = threadIdx.x;
    int i = blk * 256 + t;
    int c = (i < NN) ? g_cnt[i] : 0;

    int lane = t & 31, w = t >> 5;
    int v = c;
#pragma unroll
    for (int o = 1; o < 32; o <<= 1) {
        int u = __shfl_up_sync(0xffffffffu, v, o);
        if (lane >= o) v += u;
    }
    __shared__ int wsum[8];
    if (lane == 31) wsum[w] = v;
    __syncthreads();
    if (w == 0 && lane < 8) {
        int s = wsum[lane];
#pragma unroll
        for (int o = 1; o < 8; o <<= 1) {
            int u = __shfl_up_sync(0xffu, s, o);
            if (lane >= o) s += u;
        }
        wsum[lane] = s;
    }
    __syncthreads();
    int incl = v + ((w > 0) ? wsum[w - 1] : 0);
    if (i < NN) g_off[i] = incl - c;         // exclusive within block
    if (t == 255) g_bsum[blk] = incl;        // block total
}

// ---------------- stage 2: scan the 196 block totals (one block) ----------------
__global__ void scan2_kernel() {
    int t = threadIdx.x;  // 256
    int c = (t < NB) ? g_bsum[t] : 0;
    int lane = t & 31, w = t >> 5;
    int v = c;
#pragma unroll
    for (int o = 1; o < 32; o <<= 1) {
        int u = __shfl_up_sync(0xffffffffu, v, o);
        if (lane >= o) v += u;
    }
    __shared__ int wsum[8];
    if (lane == 31) wsum[w] = v;
    __syncthreads();
    if (w == 0 && lane < 8) {
        int s = wsum[lane];
#pragma unroll
        for (int o = 1; o < 8; o <<= 1) {
            int u = __shfl_up_sync(0xffu, s, o);
            if (lane >= o) s += u;
        }
        wsum[lane] = s;
    }
    __syncthreads();
    int incl = v + ((w > 0) ? wsum[w - 1] : 0);
    if (t < NB) g_bpre[t] = incl - c;        // exclusive block prefix
}

// ---------------- stage 3: finalize offsets, cursors, inverse degree ----------------
__global__ void scan3_kernel() {
    int i = blockIdx.x * blockDim.x + threadIdx.x;
    if (i < NN) {
        int o = g_off[i] + g_bpre[i >> 8];
        g_off[i] = o;
        g_pos[i] = o;
        g_inv[i] = 1.0f / fmaxf((float)g_cnt[i], 1.0f);
    }
}

// ---------------- CSR fill ----------------
__global__ void fill_kernel(const int* __restrict__ src,
                            const int* __restrict__ tgt) {
    int e = blockIdx.x * blockDim.x + threadIdx.x;
    if (e < EE) {
        int p = atomicAdd(&g_pos[tgt[e]], 1);
        g_adj[p] = src[e];
    }
}

// ---------------- gather: agg[n] = mean over in-neighbors of h[src] ----------------
template <int WHICH>
__global__ void gather_kernel() {
    const float* __restrict__ h = (WHICH == 0) ? g_h0 : g_h1;
    int idx = blockIdx.x * blockDim.x + threadIdx.x;
    int node = idx >> 5;
    if (node >= NN) return;
    int lane = idx & 31;

    int beg = g_off[node];
    int cnt = g_cnt[node];
    float4 acc = make_float4(0.f, 0.f, 0.f, 0.f);

    int i = 0;
    for (; i + 4 <= cnt; i += 4) {
        int s0 = __ldg(&g_adj[beg + i + 0]);
        int s1 = __ldg(&g_adj[beg + i + 1]);
        int s2 = __ldg(&g_adj[beg + i + 2]);
        int s3 = __ldg(&g_adj[beg + i + 3]);
        float4 v0 = *reinterpret_cast<const float4*>(h + s0 * HH + lane * 4);
        float4 v1 = *reinterpret_cast<const float4*>(h + s1 * HH + lane * 4);
        float4 v2 = *reinterpret_cast<const float4*>(h + s2 * HH + lane * 4);
        float4 v3 = *reinterpret_cast<const float4*>(h + s3 * HH + lane * 4);
        acc.x += v0.x + v1.x + v2.x + v3.x;
        acc.y += v0.y + v1.y + v2.y + v3.y;
        acc.z += v0.z + v1.z + v2.z + v3.z;
        acc.w += v0.w + v1.w + v2.w + v3.w;
    }
    for (; i < cnt; i++) {
        int s = __ldg(&g_adj[beg + i]);
        float4 v = *reinterpret_cast<const float4*>(h + s * HH + lane * 4);
        acc.x += v.x; acc.y += v.y; acc.z += v.z; acc.w += v.w;
    }
    float iv = g_inv[node];
    acc.x *= iv; acc.y *= iv; acc.z *= iv; acc.w *= iv;
    *reinterpret_cast<float4*>(g_agg + node * HH + lane * 4) = acc;
}

// ---------------- fused GCN layer (FFMA2 GEMM + LN [+relu+residual]) ----------------
template <int LAYER>
__global__ void __launch_bounds__(512, 1)
gcn_kernel(const float* __restrict__ ws, const float* __restrict__ bs,
           const float* __restrict__ wn, const float* __restrict__ bn,
           const float* __restrict__ gamma, const float* __restrict__ beta,
           float* __restrict__ out_param) {
    extern __shared__ float sm[];
    float* sWs = sm;                     // 16384 floats: packed [k4][j][4]
    float* sWn = sm + HH * HH;           // 16384 floats
    float* sH  = sm + 2 * HH * HH;       // 64 x 128 staged h rows (aliased by sOB)
    float* sA  = sH + 64 * HH;           // 64 x 128 staged agg rows
    float* sOB = sH;                     // pre-LN outputs alias sH

    const float* __restrict__ h_in = (LAYER == 0) ? g_h0 : g_h1;
    float* __restrict__ out = (LAYER == 0) ? g_h1 : out_param;

    int tid = threadIdx.x;

    // pack weights: sW[(k>>2)*512 + j*4 + (k&3)] = w[k*128 + j]
    for (int i = tid; i < HH * HH; i += 512) {
        int k = i >> 7, j = i & 127;
        int d = ((k >> 2) * HH + j) * 4 + (k & 3);
        sWs[d] = ws[i];
        sWn[d] = wn[i];
    }

    int j = tid & 63;   // column pair (j, j+64)
    int g = tid >> 6;   // node group 0..7
    float bias0 = __ldg(&bs[j]) + __ldg(&bn[j]);
    float bias1 = __ldg(&bs[j + 64]) + __ldg(&bn[j + 64]);

    int lane = tid & 31;
    int warp = tid >> 5;  // 0..15; each warp LNs 4 nodes
    float ga[4], be[4];
#pragma unroll
    for (int m = 0; m < 4; m++) {
        ga[m] = __ldg(&gamma[lane + 32 * m]);
        be[m] = __ldg(&beta[lane + 32 * m]);
    }
    __syncthreads();

    const ulonglong2* Ws2 = reinterpret_cast<const ulonglong2*>(sWs);
    const ulonglong2* Wn2 = reinterpret_cast<const ulonglong2*>(sWn);
    const ulonglong2* H2  = reinterpret_cast<const ulonglong2*>(sH);
    const ulonglong2* A2  = reinterpret_cast<const ulonglong2*>(sA);

    const int NT = (NN + 63) / 64;  // 782 tiles
    for (int tile = blockIdx.x; tile < NT; tile += gridDim.x) {
        int base = tile * 64;

        // ---- stage 64 node rows of h and agg (zeros for OOB) ----
        {
            int row = tid >> 3;            // 0..63
            int c4 = (tid & 7) * 4;        // float4 col base
            int node = base + row;
            float4 z = make_float4(0.f, 0.f, 0.f, 0.f);
#pragma unroll
            for (int q = 0; q < 4; q++) {
                float4 hv = z, av = z;
                if (node < NN) {
                    hv = *reinterpret_cast<const float4*>(h_in + node * HH + (c4 + q) * 4);
                    av = *reinterpret_cast<const float4*>(g_agg + node * HH + (c4 + q) * 4);
                }
                reinterpret_cast<float4*>(sH)[row * 32 + c4 + q] = hv;
                reinterpret_cast<float4*>(sA)[row * 32 + c4 + q] = av;
            }
        }
        __syncthreads();

        // ---- packed GEMM: 8 nodes x 2 cols per thread ----
        unsigned long long acc0[8], acc1[8];
#pragma unroll
        for (int i = 0; i < 8; i++) { acc0[i] = 0ull; acc1[i] = 0ull; }

        for (int k4 = 0; k4 < 32; k4++) {
            ulonglong2 wsa = Ws2[k4 * HH + j];
            ulonglong2 wsb = Ws2[k4 * HH + j + 64];
            ulonglong2 wna = Wn2[k4 * HH + j];
            ulonglong2 wnb = Wn2[k4 * HH + j + 64];
#pragma unroll
            for (int i = 0; i < 8; i++) {
                ulonglong2 hv = H2[(g * 8 + i) * 32 + k4];
                ulonglong2 av = A2[(g * 8 + i) * 32 + k4];
                fma2(acc0[i], hv.x, wsa.x);
                fma2(acc0[i], hv.y, wsa.y);
                fma2(acc0[i], av.x, wna.x);
                fma2(acc0[i], av.y, wna.y);
                fma2(acc1[i], hv.x, wsb.x);
                fma2(acc1[i], hv.y, wsb.y);
                fma2(acc1[i], av.x, wnb.x);
                fma2(acc1[i], av.y, wnb.y);
            }
        }
        __syncthreads();  // everyone done reading sH/sA before sOB aliasing write

#pragma unroll
        for (int i = 0; i < 8; i++) {
            int row = g * 8 + i;
            sOB[row * HH + j]      = f2fold(acc0[i], bias0);
            sOB[row * HH + j + 64] = f2fold(acc1[i], bias1);
        }
        __syncthreads();

        // ---- LayerNorm (+ relu + residual for layer 0): warp handles 4 nodes ----
#pragma unroll
        for (int it = 0; it < 4; it++) {
            int row = warp * 4 + it;
            int node = base + row;
            if (node < NN) {
                float v[4];
                float s = 0.f, q = 0.f;
#pragma unroll
                for (int m = 0; m < 4; m++) {
                    v[m] = sOB[row * HH + lane + 32 * m];
                    s += v[m];
                    q += v[m] * v[m];
                }
#pragma unroll
                for (int o = 16; o > 0; o >>= 1) {
                    s += __shfl_xor_sync(0xffffffffu, s, o);
                    q += __shfl_xor_sync(0xffffffffu, q, o);
                }
                float mean = s * (1.0f / HH);
                float var = q * (1.0f / HH) - mean * mean;
                float rstd = rsqrtf(var + LN_EPS);
#pragma unroll
                for (int m = 0; m < 4; m++) {
                    float y = (v[m] - mean) * rstd * ga[m] + be[m];
                    if (LAYER == 0)
                        y = fmaxf(y, 0.f) + h_in[node * HH + lane + 32 * m];
                    out[node * HH + lane + 32 * m] = y;
                }
            }
        }
        __syncthreads();  // protect sOB/sA before next tile staging
    }
}

// ---------------- launch ----------------
extern "C" void kernel_launch(void* const* d_in, const int* in_sizes, int n_in,
                              void* d_out, int out_size) {
    const float* x    = (const float*)d_in[0];
    const int*   ei   = (const int*)d_in[1];
    const float* w_in = (const float*)d_in[2];
    const float* b_in = (const float*)d_in[3];
    const float* ws0  = (const float*)d_in[4];
    const float* bs0  = (const float*)d_in[5];
    const float* wn0  = (const float*)d_in[6];
    const float* bn0  = (const float*)d_in[7];
    const float* g0   = (const float*)d_in[8];
    const float* be0  = (const float*)d_in[9];
    const float* ws1  = (const float*)d_in[10];
    const float* bs1  = (const float*)d_in[11];
    const float* wn1  = (const float*)d_in[12];
    const float* bn1  = (const float*)d_in[13];
    const float* g1   = (const float*)d_in[14];
    const float* be1  = (const float*)d_in[15];
    float* out = (float*)d_out;

    const int* src = ei;
    const int* tgt = ei + EE;

    const int SMEM = (2 * HH * HH + 2 * 64 * HH) * (int)sizeof(float);  // 196608 B
    cudaFuncSetAttribute(gcn_kernel<0>, cudaFuncAttributeMaxDynamicSharedMemorySize, SMEM);
    cudaFuncSetAttribute(gcn_kernel<1>, cudaFuncAttributeMaxDynamicSharedMemorySize, SMEM);

    zero_cnt_kernel<<<(NN + 255) / 256, 256>>>();
    input_proj_kernel<<<512, 256>>>(x, w_in, b_in);
    count_kernel<<<(EE + 255) / 256, 256>>>(tgt);
    scan1_kernel<<<NB, 256>>>();
    scan2_kernel<<<1, 256>>>();
    scan3_kernel<<<NB, 256>>>();
    fill_kernel<<<(EE + 255) / 256, 256>>>(src, tgt);
    gather_kernel<0><<<(NN * 32 + 255) / 256, 256>>>();
    gcn_kernel<0><<<148, 512, SMEM>>>(ws0, bs0, wn0, bn0, g0, be0, nullptr);
    gather_kernel<1><<<(NN * 32 + 255) / 256, 256>>>();
    gcn_kernel<1><<<148, 512, SMEM>>>(ws1, bs1, wn1, bn1, g1, be1, out);
}

// round 11
// speedup vs baseline: 2.6381x; 1.6735x over previous
#include <cuda_runtime.h>
#include <cuda_bf16.h>
#include <cstdint>

#define NN   50000
#define EE   800000
#define FIN  32
#define HH   128
#define LN_EPS 1e-5f
#define NB   ((NN + 255) / 256)   // 196 scan blocks
#define NTILES ((NN + 127) / 128) // 391 GEMM tiles

// ---------------- scratch (static device allocations only) ----------------
__device__ float g_h0[NN * HH];
__device__ float g_h1[NN * HH];
__device__ float g_agg[NN * HH];
__device__ float g_inv[NN];
__device__ int   g_cnt[NN];
__device__ int   g_off[NN];
__device__ int   g_pos[NN];
__device__ int   g_adj[EE];
__device__ int   g_bsum[NB];
__device__ int   g_bpre[NB];

// ---------------- mma.sync tf32 helpers ----------------
__device__ __forceinline__ uint32_t f2tf32(float x) {
    uint32_t r;
    asm("cvt.rna.tf32.f32 %0, %1;" : "=r"(r) : "f"(x));
    return r;
}

__device__ __forceinline__ void mma_tf32(float* acc, uint32_t a0, uint32_t a1,
                                         uint32_t a2, uint32_t a3,
                                         uint32_t b0, uint32_t b1) {
    asm volatile(
        "mma.sync.aligned.m16n8k8.row.col.f32.tf32.tf32.f32 "
        "{%0,%1,%2,%3}, {%4,%5,%6,%7}, {%8,%9}, {%0,%1,%2,%3};"
        : "+f"(acc[0]), "+f"(acc[1]), "+f"(acc[2]), "+f"(acc[3])
        : "r"(a0), "r"(a1), "r"(a2), "r"(a3), "r"(b0), "r"(b1));
}

// ---------------- zero degree counters ----------------
__global__ void zero_cnt_kernel() {
    int i = blockIdx.x * blockDim.x + threadIdx.x;
    if (i < NN) g_cnt[i] = 0;
}

// ---------------- input projection ----------------
__global__ void input_proj_kernel(const float* __restrict__ x,
                                  const float* __restrict__ w,
                                  const float* __restrict__ b) {
    __shared__ float sw[FIN * HH];
    __shared__ float sb[HH];
    int tid = threadIdx.x;
    for (int i = tid; i < FIN * HH; i += 256) sw[i] = w[i];
    if (tid < HH) sb[tid] = b[tid];
    __syncthreads();

    int j = tid & 127;
    int half = tid >> 7;
    for (int n = blockIdx.x * 2 + half; n < NN; n += gridDim.x * 2) {
        const float4* xr = reinterpret_cast<const float4*>(x + n * FIN);
        float acc = sb[j];
#pragma unroll
        for (int k4 = 0; k4 < FIN / 4; k4++) {
            float4 xv = xr[k4];
            int k = k4 * 4;
            acc = fmaf(xv.x, sw[(k + 0) * HH + j], acc);
            acc = fmaf(xv.y, sw[(k + 1) * HH + j], acc);
            acc = fmaf(xv.z, sw[(k + 2) * HH + j], acc);
            acc = fmaf(xv.w, sw[(k + 3) * HH + j], acc);
        }
        g_h0[n * HH + j] = fmaxf(acc, 0.f);
    }
}

// ---------------- degree count ----------------
__global__ void count_kernel(const int* __restrict__ tgt) {
    int i = blockIdx.x * blockDim.x + threadIdx.x;
    if (i < EE) atomicAdd(&g_cnt[tgt[i]], 1);
}

// ---------------- parallel scan ----------------
__global__ void scan1_kernel() {
    int blk = blockIdx.x;
    int t = threadIdx.x;
    int i = blk * 256 + t;
    int c = (i < NN) ? g_cnt[i] : 0;

    int lane = t & 31, w = t >> 5;
    int v = c;
#pragma unroll
    for (int o = 1; o < 32; o <<= 1) {
        int u = __shfl_up_sync(0xffffffffu, v, o);
        if (lane >= o) v += u;
    }
    __shared__ int wsum[8];
    if (lane == 31) wsum[w] = v;
    __syncthreads();
    if (w == 0 && lane < 8) {
        int s = wsum[lane];
#pragma unroll
        for (int o = 1; o < 8; o <<= 1) {
            int u = __shfl_up_sync(0xffu, s, o);
            if (lane >= o) s += u;
        }
        wsum[lane] = s;
    }
    __syncthreads();
    int incl = v + ((w > 0) ? wsum[w - 1] : 0);
    if (i < NN) g_off[i] = incl - c;
    if (t == 255) g_bsum[blk] = incl;
}

__global__ void scan2_kernel() {
    int t = threadIdx.x;
    int c = (t < NB) ? g_bsum[t] : 0;
    int lane = t & 31, w = t >> 5;
    int v = c;
#pragma unroll
    for (int o = 1; o < 32; o <<= 1) {
        int u = __shfl_up_sync(0xffffffffu, v, o);
        if (lane >= o) v += u;
    }
    __shared__ int wsum[8];
    if (lane == 31) wsum[w] = v;
    __syncthreads();
    if (w == 0 && lane < 8) {
        int s = wsum[lane];
#pragma unroll
        for (int o = 1; o < 8; o <<= 1) {
            int u = __shfl_up_sync(0xffu, s, o);
            if (lane >= o) s += u;
        }
        wsum[lane] = s;
    }
    __syncthreads();
    int incl = v + ((w > 0) ? wsum[w - 1] : 0);
    if (t < NB) g_bpre[t] = incl - c;
}

__global__ void scan3_kernel() {
    int i = blockIdx.x * blockDim.x + threadIdx.x;
    if (i < NN) {
        int o = g_off[i] + g_bpre[i >> 8];
        g_off[i] = o;
        g_pos[i] = o;
        g_inv[i] = 1.0f / fmaxf((float)g_cnt[i], 1.0f);
    }
}

// ---------------- CSR fill ----------------
__global__ void fill_kernel(const int* __restrict__ src,
                            const int* __restrict__ tgt) {
    int e = blockIdx.x * blockDim.x + threadIdx.x;
    if (e < EE) {
        int p = atomicAdd(&g_pos[tgt[e]], 1);
        g_adj[p] = src[e];
    }
}

// ---------------- gather ----------------
template <int WHICH>
__global__ void gather_kernel() {
    const float* __restrict__ h = (WHICH == 0) ? g_h0 : g_h1;
    int idx = blockIdx.x * blockDim.x + threadIdx.x;
    int node = idx >> 5;
    if (node >= NN) return;
    int lane = idx & 31;

    int beg = g_off[node];
    int cnt = g_cnt[node];
    float4 acc = make_float4(0.f, 0.f, 0.f, 0.f);

    int i = 0;
    for (; i + 4 <= cnt; i += 4) {
        int s0 = __ldg(&g_adj[beg + i + 0]);
        int s1 = __ldg(&g_adj[beg + i + 1]);
        int s2 = __ldg(&g_adj[beg + i + 2]);
        int s3 = __ldg(&g_adj[beg + i + 3]);
        float4 v0 = *reinterpret_cast<const float4*>(h + s0 * HH + lane * 4);
        float4 v1 = *reinterpret_cast<const float4*>(h + s1 * HH + lane * 4);
        float4 v2 = *reinterpret_cast<const float4*>(h + s2 * HH + lane * 4);
        float4 v3 = *reinterpret_cast<const float4*>(h + s3 * HH + lane * 4);
        acc.x += v0.x + v1.x + v2.x + v3.x;
        acc.y += v0.y + v1.y + v2.y + v3.y;
        acc.z += v0.z + v1.z + v2.z + v3.z;
        acc.w += v0.w + v1.w + v2.w + v3.w;
    }
    for (; i < cnt; i++) {
        int s = __ldg(&g_adj[beg + i]);
        float4 v = *reinterpret_cast<const float4*>(h + s * HH + lane * 4);
        acc.x += v.x; acc.y += v.y; acc.z += v.z; acc.w += v.w;
    }
    float iv = g_inv[node];
    acc.x *= iv; acc.y *= iv; acc.z *= iv; acc.w *= iv;
    *reinterpret_cast<float4*>(g_agg + node * HH + lane * 4) = acc;
}

// ================= fused GCN layer via mma.sync tf32 =================
// 512 threads = 16 warps: warp grid 8 (m) x 2 (n); warp tile 16 x 64.
// CTA tile: 128 nodes x 128 cols; K = 128 per matrix, 2 matrices (h@ws + agg@wn).
//
// smem (floats):
//   [0, 32768)        B fragments (float2 x 16384): ((mat*16+s)*16+nf)*32+lane
//   [32768, 49664)    A tile row-major padded [128][132] (tf32-converted)
//   [49664, 49920)    sredS [128][2]
//   [49920, 50176)    sredQ [128][2]
//   [50176, 50304)    gamma
//   [50304, 50432)    beta
//   [50432, 50560)    bias (bs+bn)
// total 50560 floats = 202240 B
#define SM_B2_F   0
#define SM_A_F    32768
#define SM_RS_F   49664
#define SM_RQ_F   49920
#define SM_G_F    50176
#define SM_BE_F   50304
#define SM_BI_F   50432
#define GCN_SMEM  (50560 * 4)
#define APITCH    132

template <int LAYER>
__global__ void __launch_bounds__(512, 1)
gcn_kernel(const float* __restrict__ ws, const float* __restrict__ bs,
           const float* __restrict__ wn, const float* __restrict__ bn,
           const float* __restrict__ gamma, const float* __restrict__ beta,
           float* __restrict__ out_param) {
    extern __shared__ float sm[];
    float2* B2   = reinterpret_cast<float2*>(sm + SM_B2_F);
    float*  sA   = sm + SM_A_F;
    float*  sredS = sm + SM_RS_F;
    float*  sredQ = sm + SM_RQ_F;
    float*  sg   = sm + SM_G_F;
    float*  sbe  = sm + SM_BE_F;
    float*  sbias = sm + SM_BI_F;

    const float* __restrict__ h_in = (LAYER == 0) ? g_h0 : g_h1;
    float* __restrict__ out = (LAYER == 0) ? g_h1 : out_param;

    int tid = threadIdx.x;
    int lane = tid & 31, wid = tid >> 5;
    int mr = wid >> 1;          // m row-group 0..7 (rows mr*16 .. mr*16+15)
    int wc = wid & 1;           // n col-group 0..1 (cols wc*64 .. wc*64+63)
    int ql = lane & 3, qr = lane >> 2;

    // ---- one-time: permute weights into B-fragment layout ----
    // b0 = w[k][n], b1 = w[k+4][n]; k = s*8+ql, n = nf*8+qr
    for (int e = tid; e < 16384; e += 512) {
        int l  = e & 31;
        int nf = (e >> 5) & 15;
        int s  = (e >> 9) & 15;
        int mat = e >> 13;
        const float* __restrict__ w = mat ? wn : ws;
        int k = s * 8 + (l & 3);
        int n = nf * 8 + (l >> 2);
        float2 b;
        b.x = __uint_as_float(f2tf32(w[k * HH + n]));
        b.y = __uint_as_float(f2tf32(w[(k + 4) * HH + n]));
        B2[e] = b;
    }
    for (int i = tid; i < HH; i += 512) {
        sg[i] = gamma[i];
        sbe[i] = beta[i];
        sbias[i] = bs[i] + bn[i];
    }
    __syncthreads();

    for (int tile = blockIdx.x; tile < NTILES; tile += gridDim.x) {
        int base = tile * 128;

        float acc[8][4];
#pragma unroll
        for (int nf = 0; nf < 8; nf++)
#pragma unroll
            for (int i = 0; i < 4; i++) acc[nf][i] = 0.f;

#pragma unroll
        for (int mat = 0; mat < 2; mat++) {
            // ---- stage A tile (coalesced read, tf32 convert, padded store) ----
            const float* __restrict__ src = mat ? g_agg : h_in;
#pragma unroll
            for (int q = 0; q < 8; q++) {
                int id = q * 512 + tid;       // 4096 float4 slots
                int r = id >> 5, c4 = (id & 31) * 4;
                int node = base + r;
                float4 v = make_float4(0.f, 0.f, 0.f, 0.f);
                if (node < NN)
                    v = *reinterpret_cast<const float4*>(src + node * HH + c4);
                float4 t;
                t.x = __uint_as_float(f2tf32(v.x));
                t.y = __uint_as_float(f2tf32(v.y));
                t.z = __uint_as_float(f2tf32(v.z));
                t.w = __uint_as_float(f2tf32(v.w));
                *reinterpret_cast<float4*>(sA + r * APITCH + c4) = t;
            }
            __syncthreads();

            // ---- K loop: 16 k8-steps ----
            int r0 = mr * 16 + qr;
            for (int s = 0; s < 16; s++) {
                int k = s * 8 + ql;
                uint32_t a0 = __float_as_uint(sA[r0 * APITCH + k]);
                uint32_t a1 = __float_as_uint(sA[(r0 + 8) * APITCH + k]);
                uint32_t a2 = __float_as_uint(sA[r0 * APITCH + k + 4]);
                uint32_t a3 = __float_as_uint(sA[(r0 + 8) * APITCH + k + 4]);
                const float2* bp = B2 + ((mat * 16 + s) * 16 + wc * 8) * 32 + lane;
#pragma unroll
                for (int nf = 0; nf < 8; nf++) {
                    float2 b = bp[nf * 32];
                    mma_tf32(acc[nf], a0, a1, a2, a3,
                             __float_as_uint(b.x), __float_as_uint(b.y));
                }
            }
            __syncthreads();
        }

        // ---- epilogue: +bias, LN stats, normalize, [relu+residual], store ----
        int row_lo = mr * 16 + qr;
        int row_hi = row_lo + 8;
        float s_lo = 0.f, q_lo = 0.f, s_hi = 0.f, q_hi = 0.f;
#pragma unroll
        for (int nf = 0; nf < 8; nf++) {
            int c0 = wc * 64 + nf * 8 + 2 * ql;
            acc[nf][0] += sbias[c0];
            acc[nf][1] += sbias[c0 + 1];
            acc[nf][2] += sbias[c0];
            acc[nf][3] += sbias[c0 + 1];
            s_lo += acc[nf][0] + acc[nf][1];
            q_lo += acc[nf][0] * acc[nf][0] + acc[nf][1] * acc[nf][1];
            s_hi += acc[nf][2] + acc[nf][3];
            q_hi += acc[nf][2] * acc[nf][2] + acc[nf][3] * acc[nf][3];
        }
#pragma unroll
        for (int o = 1; o <= 2; o <<= 1) {
            s_lo += __shfl_xor_sync(0xffffffffu, s_lo, o);
            q_lo += __shfl_xor_sync(0xffffffffu, q_lo, o);
            s_hi += __shfl_xor_sync(0xffffffffu, s_hi, o);
            q_hi += __shfl_xor_sync(0xffffffffu, q_hi, o);
        }
        if (ql == 0) {
            sredS[row_lo * 2 + wc] = s_lo;
            sredQ[row_lo * 2 + wc] = q_lo;
            sredS[row_hi * 2 + wc] = s_hi;
            sredQ[row_hi * 2 + wc] = q_hi;
        }
        __syncthreads();
        float S_lo = sredS[row_lo * 2] + sredS[row_lo * 2 + 1];
        float Q_lo = sredQ[row_lo * 2] + sredQ[row_lo * 2 + 1];
        float S_hi = sredS[row_hi * 2] + sredS[row_hi * 2 + 1];
        float Q_hi = sredQ[row_hi * 2] + sredQ[row_hi * 2 + 1];
        float mean_lo = S_lo * (1.0f / HH);
        float var_lo = Q_lo * (1.0f / HH) - mean_lo * mean_lo;
        float rstd_lo = rsqrtf(var_lo + LN_EPS);
        float mean_hi = S_hi * (1.0f / HH);
        float var_hi = Q_hi * (1.0f / HH) - mean_hi * mean_hi;
        float rstd_hi = rsqrtf(var_hi + LN_EPS);

        int node_lo = base + row_lo;
        int node_hi = base + row_hi;
#pragma unroll
        for (int nf = 0; nf < 8; nf++) {
            int c0 = wc * 64 + nf * 8 + 2 * ql;
            float g0v = sg[c0], g1v = sg[c0 + 1];
            float b0v = sbe[c0], b1v = sbe[c0 + 1];
            if (node_lo < NN) {
                float2 y;
                y.x = (acc[nf][0] - mean_lo) * rstd_lo * g0v + b0v;
                y.y = (acc[nf][1] - mean_lo) * rstd_lo * g1v + b1v;
                if (LAYER == 0) {
                    float2 res = *reinterpret_cast<const float2*>(
                        h_in + node_lo * HH + c0);
                    y.x = fmaxf(y.x, 0.f) + res.x;
                    y.y = fmaxf(y.y, 0.f) + res.y;
                }
                *reinterpret_cast<float2*>(out + node_lo * HH + c0) = y;
            }
            if (node_hi < NN) {
                float2 y;
                y.x = (acc[nf][2] - mean_hi) * rstd_hi * g0v + b0v;
                y.y = (acc[nf][3] - mean_hi) * rstd_hi * g1v + b1v;
                if (LAYER == 0) {
                    float2 res = *reinterpret_cast<const float2*>(
                        h_in + node_hi * HH + c0);
                    y.x = fmaxf(y.x, 0.f) + res.x;
                    y.y = fmaxf(y.y, 0.f) + res.y;
                }
                *reinterpret_cast<float2*>(out + node_hi * HH + c0) = y;
            }
        }
        __syncthreads();  // protect sred / sA before next tile
    }
}

// ---------------- launch ----------------
extern "C" void kernel_launch(void* const* d_in, const int* in_sizes, int n_in,
                              void* d_out, int out_size) {
    const float* x    = (const float*)d_in[0];
    const int*   ei   = (const int*)d_in[1];
    const float* w_in = (const float*)d_in[2];
    const float* b_in = (const float*)d_in[3];
    const float* ws0  = (const float*)d_in[4];
    const float* bs0  = (const float*)d_in[5];
    const float* wn0  = (const float*)d_in[6];
    const float* bn0  = (const float*)d_in[7];
    const float* g0   = (const float*)d_in[8];
    const float* be0  = (const float*)d_in[9];
    const float* ws1  = (const float*)d_in[10];
    const float* bs1  = (const float*)d_in[11];
    const float* wn1  = (const float*)d_in[12];
    const float* bn1  = (const float*)d_in[13];
    const float* g1   = (const float*)d_in[14];
    const float* be1  = (const float*)d_in[15];
    float* out = (float*)d_out;

    const int* src = ei;
    const int* tgt = ei + EE;

    cudaFuncSetAttribute(gcn_kernel<0>, cudaFuncAttributeMaxDynamicSharedMemorySize, GCN_SMEM);
    cudaFuncSetAttribute(gcn_kernel<1>, cudaFuncAttributeMaxDynamicSharedMemorySize, GCN_SMEM);

    zero_cnt_kernel<<<(NN + 255) / 256, 256>>>();
    input_proj_kernel<<<512, 256>>>(x, w_in, b_in);
    count_kernel<<<(EE + 255) / 256, 256>>>(tgt);
    scan1_kernel<<<NB, 256>>>();
    scan2_kernel<<<1, 256>>>();
    scan3_kernel<<<NB, 256>>>();
    fill_kernel<<<(EE + 255) / 256, 256>>>(src, tgt);
    gather_kernel<0><<<(NN * 32 + 255) / 256, 256>>>();
    gcn_kernel<0><<<148, 512, GCN_SMEM>>>(ws0, bs0, wn0, bn0, g0, be0, nullptr);
    gather_kernel<1><<<(NN * 32 + 255) / 256, 256>>>();
    gcn_kernel<1><<<148, 512, GCN_SMEM>>>(ws1, bs1, wn1, bn1, g1, be1, out);
}